// round 13
// baseline (speedup 1.0000x reference)
#include <cuda_runtime.h>
#include <stdint.h>

#define BB 16
#define CC 19
#define HH 512
#define WW 512
#define KX 4
#define WSEG 4            // 512 / (32*KX)
#define HCH 8
#define HROWS (HH/HCH)    // 64
#define WPB 4             // warps per block (128 threads)
#define NWARPS (BB*CC*WSEG*HCH)   // 9728
#define NBLOCKS (NWARPS/WPB)      // 2432

#define B01   0x01010101u
#define TPAD  64          // front pad so (tp + dL) stays in-array at b=0,row=0

__device__ unsigned char g_tgt8[TPAD + BB*HH*WW];  // 4 MB scratch + pad
__device__ double g_acc;                     // zero-init; edge's last block resets
__device__ unsigned g_ticket;

// ---------------------------------------------------------------------------
// prep: detect int64-vs-int32 targets and convert to uint8 (L2-resident for
// the 19x channel reuse). Sampling safe for the SMALLEST possible buffer
// (int32: 4,194,304 words). int64 -> all odd words zero; int32 -> odd words
// are labels, P(all 16 samples == 0) = 19^-16 ~ 0.
// ---------------------------------------------------------------------------
__global__ void prep_kernel(const unsigned int* __restrict__ t) {
    bool is32 = false;
    #pragma unroll
    for (unsigned k = 0; k < 16; k++) {
        unsigned idx = k * 262139u + 1u;       // max 3,932,086 < 4,194,304
        is32 |= (__ldg(&t[idx | 1u]) != 0u);   // force odd
    }

    unsigned char* dst = g_tgt8 + TPAD;
    const int n4 = BB * HH * WW / 4;
    for (int i = blockIdx.x * blockDim.x + threadIdx.x; i < n4;
         i += gridDim.x * blockDim.x) {
        uchar4 o;
        if (is32) {
            uint4 v = reinterpret_cast<const uint4*>(t)[i];
            o.x = (unsigned char)v.x; o.y = (unsigned char)v.y;
            o.z = (unsigned char)v.z; o.w = (unsigned char)v.w;
        } else {
            o.x = (unsigned char)t[(4 * i + 0) * 2];
            o.y = (unsigned char)t[(4 * i + 1) * 2];
            o.z = (unsigned char)t[(4 * i + 2) * 2];
            o.w = (unsigned char)t[(4 * i + 3) * 2];
        }
        reinterpret_cast<uchar4*>(dst)[i] = o;
    }
}

// ---------------------------------------------------------------------------
// Raw row (loads only; halos via per-lane-constant deltas dL/dR that encode
// the boundary clamp) and derived per-row separable terms. Row pointers
// advance incrementally (no per-call row*WW IMAD chain).
// ---------------------------------------------------------------------------
struct Raw  { float x0, x1, x2, x3, xl, xr; unsigned t4, th; };  // th = tl|(tr<<8)
struct RowD { float a[KX], s[KX]; unsigned u, v; };

__device__ __forceinline__ void zero_raw(Raw& r) {
    r.x0 = r.x1 = r.x2 = r.x3 = r.xl = r.xr = 0.f;
    r.t4 = 0xFFFFFFFFu; r.th = 0xFFFFu;         // 255 != any class
}

__device__ __forceinline__ void load_row(
    Raw& r, const float*& p, const unsigned char*& tp,
    int dL, int dR, float lm, float rm, unsigned bmask)
{
    float4 xv = *reinterpret_cast<const float4*>(p);
    // Halo loads hit the same L1 lines the float4s pulled. dL/dR encode the
    // boundary clamp (0 at edges); boundary VALUE handled by lm/rm/bmask.
    r.xl = __ldg(p + dL) * lm;          // lm=0 at left edge -> exact 0
    r.xr = __ldg(p + dR) * rm;
    r.x0 = xv.x; r.x1 = xv.y; r.x2 = xv.z; r.x3 = xv.w;

    unsigned t4 = *reinterpret_cast<const unsigned*>(tp);
    unsigned tl = (unsigned)__ldg(tp + dL);
    unsigned tr = (unsigned)__ldg(tp + dR);
    r.t4 = t4;
    r.th = __byte_perm(tl, tr, 0x7740u) | bmask;  // (tl,tr,0,0) | edge-sat

    p  += WW;                            // advance to next row
    tp += WW;
}

__device__ __forceinline__ void derive(RowD& d, const Raw& r, unsigned cc4) {
    // input: diff-x / smooth-x
    d.a[0] = r.x1 - r.xl;  d.a[1] = r.x2 - r.x0;
    d.a[2] = r.x3 - r.x1;  d.a[3] = r.xr - r.x2;
    d.s[0] = fmaf(2.f, r.x0, r.xl + r.x1);
    d.s[1] = fmaf(2.f, r.x1, r.x0 + r.x2);
    d.s[2] = fmaf(2.f, r.x2, r.x1 + r.x3);
    d.s[3] = fmaf(2.f, r.x3, r.x2 + r.xr);
    // target: 2 byte-compares, then permute the MASKS for shifted windows
    unsigned m01 = __vcmpeq4(r.t4, cc4) & B01;            // masks of t0..t3
    unsigned mh  = __vcmpeq4(r.th, cc4) & 0x00000101u;    // b0=ml, b1=mr
    unsigned ml01 = __byte_perm(m01, mh, 0x2104);  // (ml, m0, m1, m2)
    unsigned mr01 = __byte_perm(m01, mh, 0x5321);  // (m1, m2, m3, mr)
    d.u = (mr01 + B01) - ml01;            // per-byte u+1, in [0,2]; no borrow
    d.v = ml01 + mr01 + m01 * 2u;         // per-byte, in [0,4]; IMAD-friendly
}

__device__ __forceinline__ float unpack_b(unsigned w, unsigned sel) {
    // byte -> exact float via mantissa insertion; subtract (2^23 + bias 4)
    return __uint_as_float(__byte_perm(w, 0x4B000000u, sel)) - 8388612.0f;
}

__device__ __forceinline__ void emit_row(
    const RowD& P, const RowD& C0, const RowD& N, float& acc0, float& acc1)
{
    // packed target gradients, per-byte biased by +4, range [0,8]: carry-free
    unsigned gxt_b = C0.u * 2u + P.u + N.u;     // IMAD + IADD3
    unsigned gyt_b = (N.v + 0x04040404u) - P.v;
    #pragma unroll
    for (int i = 0; i < KX; i++) {
        float gx  = fmaf(2.f, C0.a[i], P.a[i] + N.a[i]);
        float gy  = N.s[i] - P.s[i];
        float ein = fabsf(gx) + fabsf(gy);
        unsigned sel = 0x7440u + (unsigned)i;
        float etg = fabsf(unpack_b(gxt_b, sel)) + fabsf(unpack_b(gyt_b, sel));
        float d = ein - etg;
        if (i & 1) acc1 = fmaf(d, d, acc1);
        else       acc0 = fmaf(d, d, acc0);
    }
}

__global__ __launch_bounds__(WPB * 32, 8)
void edge_kernel(const float* __restrict__ inp, float* __restrict__ out)
{
    const int warp = blockIdx.x * WPB + (threadIdx.x >> 5);
    const int lane = threadIdx.x & 31;

    const int wseg = warp & (WSEG - 1);
    const int hch  = (warp >> 2) & (HCH - 1);
    const int t2   = warp >> 5;               // = b*CC + c, in [0, 304)
    const unsigned c = (unsigned)(t2 % CC);
    const int b    = t2 / CC;
    const unsigned cc4 = c * 0x01010101u;

    const int w0 = wseg * (32 * KX) + lane * KX;
    const int dL = (w0 > 0)       ? -1 : 0;   // clamp encoded in the delta
    const int dR = (w0 + KX < WW) ? KX : 0;
    const float lm = (w0 > 0)       ? 1.f : 0.f;
    const float rm = (w0 + KX < WW) ? 1.f : 0.f;
    const unsigned bmask = ((w0 > 0) ? 0u : 0xFFu) |
                           ((w0 + KX < WW) ? 0u : 0xFF00u);
    const int h0 = hch * HROWS;

    // Row pointers start at row h0-1 and advance by WW per load.
    const float* p = inp + ((size_t)t2) * (HH * WW) + (h0 - 1) * WW + w0;
    const unsigned char* tp = g_tgt8 + TPAD + (size_t)b * (HH * WW)
                              + (h0 - 1) * WW + w0;

    float acc0 = 0.f, acc1 = 0.f;
    RowD rA, rB, rC;
    Raw q0, q1;

    // Prologue: invariant at loop top — q0 holds row y+1, q1 holds row y+2.
    // Row h0-1 is virtual-zero only for hch==0 (warp-uniform branch).
    if (hch == 0) { zero_raw(q0); p += WW; tp += WW; }
    else          { load_row(q0, p, tp, dL, dR, lm, rm, bmask); }
    load_row(q1, p, tp, dL, dR, lm, rm, bmask);     // row h0
    derive(rA, q0, cc4);
    load_row(q0, p, tp, dL, dR, lm, rm, bmask);     // row h0+1
    derive(rB, q1, cc4);
    load_row(q1, p, tp, dL, dR, lm, rm, bmask);     // row h0+2

    // 6-phase body: 10 iters = 60 rows; loads rows h0+3 .. h0+62 (all valid).
    #pragma unroll 1
    for (int it = 0; it < 10; ++it) {
        derive(rC, q0, cc4);
        load_row(q0, p, tp, dL, dR, lm, rm, bmask);
        emit_row(rA, rB, rC, acc0, acc1);
        derive(rA, q1, cc4);
        load_row(q1, p, tp, dL, dR, lm, rm, bmask);
        emit_row(rB, rC, rA, acc0, acc1);
        derive(rB, q0, cc4);
        load_row(q0, p, tp, dL, dR, lm, rm, bmask);
        emit_row(rC, rA, rB, acc0, acc1);
        derive(rC, q1, cc4);
        load_row(q1, p, tp, dL, dR, lm, rm, bmask);
        emit_row(rA, rB, rC, acc0, acc1);
        derive(rA, q0, cc4);
        load_row(q0, p, tp, dL, dR, lm, rm, bmask);
        emit_row(rB, rC, rA, acc0, acc1);
        derive(rB, q1, cc4);
        load_row(q1, p, tp, dL, dR, lm, rm, bmask);
        emit_row(rC, rA, rB, acc0, acc1);
    }
    // Epilogue: rows h0+60..63. Load h0+63 always valid; h0+64 only if hch<7.
    derive(rC, q0, cc4);
    load_row(q0, p, tp, dL, dR, lm, rm, bmask);     // row h0+63
    emit_row(rA, rB, rC, acc0, acc1);
    derive(rA, q1, cc4);
    if (hch == HCH - 1) { zero_raw(q1); }
    else                { load_row(q1, p, tp, dL, dR, lm, rm, bmask); } // h0+64
    emit_row(rB, rC, rA, acc0, acc1);
    derive(rB, q0, cc4); emit_row(rC, rA, rB, acc0, acc1);
    derive(rC, q1, cc4); emit_row(rA, rB, rC, acc0, acc1);

    // reduce: warp -> block -> global double; last block finalizes + resets.
    float acc = acc0 + acc1;
    #pragma unroll
    for (int o = 16; o; o >>= 1) acc += __shfl_xor_sync(0xffffffffu, acc, o);
    __shared__ float ws[WPB];
    if (lane == 0) ws[threadIdx.x >> 5] = acc;
    __syncthreads();
    if (threadIdx.x == 0) {
        double s = 0.0;
        #pragma unroll
        for (int i = 0; i < WPB; i++) s += (double)ws[i];
        atomicAdd(&g_acc, s);
        __threadfence();
        unsigned t = atomicAdd(&g_ticket, 1u);
        if (t == (unsigned)(NBLOCKS - 1)) {
            double v = atomicAdd(&g_acc, 0.0);   // ordered read
            out[0] = (float)(v * (1.0 / ((double)BB * HH * WW)));
            g_acc = 0.0;                          // reset for next replay
            g_ticket = 0u;
        }
    }
}

// ---------------------------------------------------------------------------
extern "C" void kernel_launch(void* const* d_in, const int* in_sizes, int n_in,
                              void* d_out, int out_size)
{
    const float* inp;
    const unsigned int* tgt;
    if (in_sizes[0] == BB * CC * HH * WW) {
        inp = (const float*)d_in[0];
        tgt = (const unsigned int*)d_in[1];
    } else {
        inp = (const float*)d_in[1];
        tgt = (const unsigned int*)d_in[0];
    }
    float* out = (float*)d_out;

    prep_kernel<<<1184, 256>>>(tgt);
    edge_kernel<<<NBLOCKS, WPB * 32>>>(inp, out);
}

// round 14
// speedup vs baseline: 1.1597x; 1.1597x over previous
#include <cuda_runtime.h>
#include <stdint.h>

#define BB 16
#define CC 19
#define HH 512
#define WW 512
#define KX 4
#define WSEG 4            // 512 / (32*KX)
#define HCH 8
#define HROWS (HH/HCH)    // 64
#define WPB 4             // warps per block (128 threads)
#define NWARPS (BB*CC*WSEG*HCH)   // 9728
#define NBLOCKS (NWARPS/WPB)      // 2432

#define B01   0x01010101u

__device__ unsigned char g_tgt8[BB*HH*WW];  // 4 MB scratch (static, allowed)
__device__ double g_acc;                     // zero-init; edge's last block resets
__device__ unsigned g_ticket;

// ---------------------------------------------------------------------------
// prep: detect int64-vs-int32 targets and convert to uint8 (L2-resident for
// the 19x channel reuse). Sampling safe for the SMALLEST possible buffer
// (int32: 4,194,304 words). int64 -> all odd words zero; int32 -> odd words
// are labels, P(all 16 samples == 0) = 19^-16 ~ 0.
// ---------------------------------------------------------------------------
__global__ void prep_kernel(const unsigned int* __restrict__ t) {
    bool is32 = false;
    #pragma unroll
    for (unsigned k = 0; k < 16; k++) {
        unsigned idx = k * 262139u + 1u;       // max 3,932,086 < 4,194,304
        is32 |= (__ldg(&t[idx | 1u]) != 0u);   // force odd
    }

    const int n4 = BB * HH * WW / 4;
    for (int i = blockIdx.x * blockDim.x + threadIdx.x; i < n4;
         i += gridDim.x * blockDim.x) {
        uchar4 o;
        if (is32) {
            uint4 v = reinterpret_cast<const uint4*>(t)[i];
            o.x = (unsigned char)v.x; o.y = (unsigned char)v.y;
            o.z = (unsigned char)v.z; o.w = (unsigned char)v.w;
        } else {
            o.x = (unsigned char)t[(4 * i + 0) * 2];
            o.y = (unsigned char)t[(4 * i + 1) * 2];
            o.z = (unsigned char)t[(4 * i + 2) * 2];
            o.w = (unsigned char)t[(4 * i + 3) * 2];
        }
        reinterpret_cast<uchar4*>(g_tgt8)[i] = o;
    }
}

// ---------------------------------------------------------------------------
// Raw row (loads only; halos via direct L1-hit neighbor loads, no shuffles)
// and derived per-row separable terms.
// Target terms byte-packed: u biased +1 per byte (in [0,2]), v in [0,4].
// ---------------------------------------------------------------------------
struct Raw  { float x0, x1, x2, x3, xl, xr; unsigned t4, th; };  // th = tl|(tr<<8)
struct RowD { float a[KX], s[KX]; unsigned u, v; };

__device__ __forceinline__ void load_row(
    Raw& r, const float* __restrict__ plane,
    const unsigned char* __restrict__ tplane,
    int row, int w0, int offL, int offR, bool lok, bool rok)
{
    if ((unsigned)row >= (unsigned)HH) {        // warp-uniform
        r.x0 = r.x1 = r.x2 = r.x3 = r.xl = r.xr = 0.f;
        r.t4 = 0xFFFFFFFFu; r.th = 0xFFFFu;     // 255 != any class
        return;
    }
    const float* xrow = plane + (size_t)row * WW;
    float4 xv = *reinterpret_cast<const float4*>(xrow + w0);
    // Neighbor-element halo loads: same L1 lines as the float4s -> hits.
    // Addresses pre-clamped in-bounds; boundary VALUE handled by select.
    float hl = __ldg(xrow + offL);
    float hr = __ldg(xrow + offR);
    r.xl = lok ? hl : 0.f;
    r.xr = rok ? hr : 0.f;
    r.x0 = xv.x; r.x1 = xv.y; r.x2 = xv.z; r.x3 = xv.w;

    const unsigned char* trow = tplane + (size_t)row * WW;
    unsigned t4 = *reinterpret_cast<const unsigned*>(trow + w0);
    unsigned tl = (unsigned)__ldg(trow + offL);
    unsigned tr = (unsigned)__ldg(trow + offR);
    r.t4 = t4;
    r.th = (lok ? tl : 0xFFu) | ((rok ? tr : 0xFFu) << 8);
}

__device__ __forceinline__ void derive(RowD& d, const Raw& r, unsigned cc4) {
    // input: diff-x / smooth-x
    d.a[0] = r.x1 - r.xl;  d.a[1] = r.x2 - r.x0;
    d.a[2] = r.x3 - r.x1;  d.a[3] = r.xr - r.x2;
    d.s[0] = fmaf(2.f, r.x0, r.xl + r.x1);
    d.s[1] = fmaf(2.f, r.x1, r.x0 + r.x2);
    d.s[2] = fmaf(2.f, r.x2, r.x1 + r.x3);
    d.s[3] = fmaf(2.f, r.x3, r.x2 + r.xr);
    // target: 2 byte-compares (center word + halo word), then permute the
    // MASKS to build the shifted windows.
    unsigned m01 = __vcmpeq4(r.t4, cc4) & B01;            // masks of t0..t3
    unsigned mh  = __vcmpeq4(r.th, cc4) & 0x00000101u;    // b0=ml, b1=mr
    unsigned ml01 = __byte_perm(m01, mh, 0x2104);  // (ml, m0, m1, m2)
    unsigned mr01 = __byte_perm(m01, mh, 0x5321);  // (m1, m2, m3, mr)
    d.u = (mr01 + B01) - ml01;            // per-byte u+1, in [0,2]; no borrow
    d.v = ml01 + mr01 + m01 * 2u;         // per-byte, in [0,4]; IMAD-friendly
}

__device__ __forceinline__ float unpack_b(unsigned w, unsigned sel) {
    // byte -> exact float via mantissa insertion; subtract (2^23 + bias 4)
    return __uint_as_float(__byte_perm(w, 0x4B000000u, sel)) - 8388612.0f;
}

__device__ __forceinline__ void emit_row(
    const RowD& P, const RowD& C0, const RowD& N, float& acc0, float& acc1)
{
    // packed target gradients, per-byte biased by +4, range [0,8]: carry-free
    unsigned gxt_b = C0.u * 2u + P.u + N.u;     // IMAD + IADD3
    unsigned gyt_b = (N.v + 0x04040404u) - P.v;
    #pragma unroll
    for (int i = 0; i < KX; i++) {
        float gx  = fmaf(2.f, C0.a[i], P.a[i] + N.a[i]);
        float gy  = N.s[i] - P.s[i];
        float ein = fabsf(gx) + fabsf(gy);
        unsigned sel = 0x7440u + (unsigned)i;
        float etg = fabsf(unpack_b(gxt_b, sel)) + fabsf(unpack_b(gyt_b, sel));
        float d = ein - etg;
        if (i & 1) acc1 = fmaf(d, d, acc1);
        else       acc0 = fmaf(d, d, acc0);
    }
}

__global__ __launch_bounds__(WPB * 32, 7)
void edge_kernel(const float* __restrict__ inp, float* __restrict__ out)
{
    const int warp = blockIdx.x * WPB + (threadIdx.x >> 5);
    const int lane = threadIdx.x & 31;

    const int wseg = warp & (WSEG - 1);
    const int hch  = (warp >> 2) & (HCH - 1);
    const int t2   = warp >> 5;               // = b*CC + c, in [0, 304)
    const unsigned c = (unsigned)(t2 % CC);
    const int b    = t2 / CC;
    const unsigned cc4 = c * 0x01010101u;

    const int wstart = wseg * (32 * KX);
    const int w0 = wstart + lane * KX;
    const bool lok = (w0 > 0);
    const bool rok = (w0 + KX < WW);
    const int offL = lok ? (w0 - 1)  : w0;    // clamped in-bounds
    const int offR = rok ? (w0 + KX) : w0;
    const int h0 = hch * HROWS;
    const float* plane = inp + ((size_t)t2) * HH * WW;
    const unsigned char* tplane = g_tgt8 + (size_t)b * HH * WW;

    float acc0 = 0.f, acc1 = 0.f;
    RowD rA, rB, rC;
    Raw q0, q1;

    // Prologue: invariant at loop top — q0 holds row y+1, q1 holds row y+2.
    load_row(q0, plane, tplane, h0 - 1, w0, offL, offR, lok, rok);
    load_row(q1, plane, tplane, h0,     w0, offL, offR, lok, rok);
    derive(rA, q0, cc4);
    load_row(q0, plane, tplane, h0 + 1, w0, offL, offR, lok, rok);
    derive(rB, q1, cc4);
    load_row(q1, plane, tplane, h0 + 2, w0, offL, offR, lok, rok);

    int y = h0;
    // 6-phase body; unroll 2 -> 12-row scheduling window for ptxas.
    #pragma unroll 2
    for (int it = 0; it < 10; ++it) {
        derive(rC, q0, cc4);
        load_row(q0, plane, tplane, y + 3, w0, offL, offR, lok, rok);
        emit_row(rA, rB, rC, acc0, acc1); ++y;
        derive(rA, q1, cc4);
        load_row(q1, plane, tplane, y + 3, w0, offL, offR, lok, rok);
        emit_row(rB, rC, rA, acc0, acc1); ++y;
        derive(rB, q0, cc4);
        load_row(q0, plane, tplane, y + 3, w0, offL, offR, lok, rok);
        emit_row(rC, rA, rB, acc0, acc1); ++y;
        derive(rC, q1, cc4);
        load_row(q1, plane, tplane, y + 3, w0, offL, offR, lok, rok);
        emit_row(rA, rB, rC, acc0, acc1); ++y;
        derive(rA, q0, cc4);
        load_row(q0, plane, tplane, y + 3, w0, offL, offR, lok, rok);
        emit_row(rB, rC, rA, acc0, acc1); ++y;
        derive(rB, q1, cc4);
        load_row(q1, plane, tplane, y + 3, w0, offL, offR, lok, rok);
        emit_row(rC, rA, rB, acc0, acc1); ++y;
    }
    // Epilogue: rows h0+60..63; loads reach exactly row h0+64 (bottom halo)
    derive(rC, q0, cc4);
    load_row(q0, plane, tplane, y + 3, w0, offL, offR, lok, rok);
    emit_row(rA, rB, rC, acc0, acc1); ++y;
    derive(rA, q1, cc4);
    load_row(q1, plane, tplane, y + 3, w0, offL, offR, lok, rok);
    emit_row(rB, rC, rA, acc0, acc1); ++y;
    derive(rB, q0, cc4); emit_row(rC, rA, rB, acc0, acc1); ++y;
    derive(rC, q1, cc4); emit_row(rA, rB, rC, acc0, acc1);

    // reduce: warp -> block -> global double; last block finalizes + resets.
    float acc = acc0 + acc1;
    #pragma unroll
    for (int o = 16; o; o >>= 1) acc += __shfl_xor_sync(0xffffffffu, acc, o);
    __shared__ float ws[WPB];
    if (lane == 0) ws[threadIdx.x >> 5] = acc;
    __syncthreads();
    if (threadIdx.x == 0) {
        double s = 0.0;
        #pragma unroll
        for (int i = 0; i < WPB; i++) s += (double)ws[i];
        atomicAdd(&g_acc, s);
        __threadfence();
        unsigned t = atomicAdd(&g_ticket, 1u);
        if (t == (unsigned)(NBLOCKS - 1)) {
            double v = atomicAdd(&g_acc, 0.0);   // ordered read
            out[0] = (float)(v * (1.0 / ((double)BB * HH * WW)));
            g_acc = 0.0;                          // reset for next replay
            g_ticket = 0u;
        }
    }
}

// ---------------------------------------------------------------------------
extern "C" void kernel_launch(void* const* d_in, const int* in_sizes, int n_in,
                              void* d_out, int out_size)
{
    const float* inp;
    const unsigned int* tgt;
    if (in_sizes[0] == BB * CC * HH * WW) {
        inp = (const float*)d_in[0];
        tgt = (const unsigned int*)d_in[1];
    } else {
        inp = (const float*)d_in[1];
        tgt = (const unsigned int*)d_in[0];
    }
    float* out = (float*)d_out;

    prep_kernel<<<1184, 256>>>(tgt);
    edge_kernel<<<NBLOCKS, WPB * 32>>>(inp, out);
}

// round 15
// speedup vs baseline: 1.2841x; 1.1072x over previous
#include <cuda_runtime.h>
#include <stdint.h>

#define BB 16
#define CC 19
#define HH 512
#define WW 512
#define KX 4
#define WSEG 4            // 512 / (32*KX)
#define HCH 8
#define HROWS (HH/HCH)    // 64
#define WPB 4             // warps per block (128 threads)
#define NWARPS (BB*CC*WSEG*HCH)   // 9728
#define NBLOCKS (NWARPS/WPB)      // 2432

#define B01   0x01010101u

__device__ unsigned char g_tgt8[BB*HH*WW];  // 4 MB scratch (static, allowed)
__device__ double g_acc;                     // zero-init; edge's last block resets
__device__ unsigned g_ticket;

// ---------------------------------------------------------------------------
// prep: detect int64-vs-int32 targets and convert to uint8 (L2-resident for
// the 19x channel reuse). Sampling safe for the SMALLEST possible buffer
// (int32: 4,194,304 words). int64 -> all odd words zero; int32 -> odd words
// are labels, P(all 16 samples == 0) = 19^-16 ~ 0.
// Both branches use uint4 vector loads.
// ---------------------------------------------------------------------------
__global__ void prep_kernel(const unsigned int* __restrict__ t) {
    bool is32 = false;
    #pragma unroll
    for (unsigned k = 0; k < 16; k++) {
        unsigned idx = k * 262139u + 1u;       // max 3,932,086 < 4,194,304
        is32 |= (__ldg(&t[idx | 1u]) != 0u);   // force odd
    }

    const int n4 = BB * HH * WW / 4;
    const uint4* tv = reinterpret_cast<const uint4*>(t);
    for (int i = blockIdx.x * blockDim.x + threadIdx.x; i < n4;
         i += gridDim.x * blockDim.x) {
        uchar4 o;
        if (is32) {
            uint4 v = tv[i];
            o.x = (unsigned char)v.x; o.y = (unsigned char)v.y;
            o.z = (unsigned char)v.z; o.w = (unsigned char)v.w;
        } else {
            uint4 v0 = tv[2 * i];              // elems 4i, 4i+1 (lo,hi pairs)
            uint4 v1 = tv[2 * i + 1];          // elems 4i+2, 4i+3
            o.x = (unsigned char)v0.x; o.y = (unsigned char)v0.z;
            o.z = (unsigned char)v1.x; o.w = (unsigned char)v1.z;
        }
        reinterpret_cast<uchar4*>(g_tgt8)[i] = o;
    }
}

// ---------------------------------------------------------------------------
// Raw row (loads only; halos via direct L1-hit neighbor loads, no shuffles)
// and derived per-row separable terms.
// Target terms byte-packed: u biased +1 per byte (in [0,2]), v in [0,4].
// ---------------------------------------------------------------------------
struct Raw  { float x0, x1, x2, x3, xl, xr; unsigned t4, th; };  // th = tl|(tr<<8)
struct RowD { float a[KX], s[KX]; unsigned u, v; };

__device__ __forceinline__ void load_row(
    Raw& r, const float* __restrict__ plane,
    const unsigned char* __restrict__ tplane,
    int row, int w0, int offL, int offR, bool lok, bool rok)
{
    if ((unsigned)row >= (unsigned)HH) {        // warp-uniform
        r.x0 = r.x1 = r.x2 = r.x3 = r.xl = r.xr = 0.f;
        r.t4 = 0xFFFFFFFFu; r.th = 0xFFFFu;     // 255 != any class
        return;
    }
    const float* xrow = plane + (size_t)row * WW;
    float4 xv = *reinterpret_cast<const float4*>(xrow + w0);
    // Neighbor-element halo loads: same L1 lines as the float4s -> hits.
    // Addresses pre-clamped in-bounds; boundary VALUE handled by select.
    float hl = __ldg(xrow + offL);
    float hr = __ldg(xrow + offR);
    r.xl = lok ? hl : 0.f;
    r.xr = rok ? hr : 0.f;
    r.x0 = xv.x; r.x1 = xv.y; r.x2 = xv.z; r.x3 = xv.w;

    const unsigned char* trow = tplane + (size_t)row * WW;
    unsigned t4 = *reinterpret_cast<const unsigned*>(trow + w0);
    unsigned tl = (unsigned)__ldg(trow + offL);
    unsigned tr = (unsigned)__ldg(trow + offR);
    r.t4 = t4;
    r.th = (lok ? tl : 0xFFu) | ((rok ? tr : 0xFFu) << 8);
}

__device__ __forceinline__ void derive(RowD& d, const Raw& r, unsigned cc4) {
    // input: diff-x / smooth-x
    d.a[0] = r.x1 - r.xl;  d.a[1] = r.x2 - r.x0;
    d.a[2] = r.x3 - r.x1;  d.a[3] = r.xr - r.x2;
    d.s[0] = fmaf(2.f, r.x0, r.xl + r.x1);
    d.s[1] = fmaf(2.f, r.x1, r.x0 + r.x2);
    d.s[2] = fmaf(2.f, r.x2, r.x1 + r.x3);
    d.s[3] = fmaf(2.f, r.x3, r.x2 + r.xr);
    // target: 2 byte-compares (center word + halo word), then permute the
    // MASKS to build the shifted windows.
    unsigned m01 = __vcmpeq4(r.t4, cc4) & B01;            // masks of t0..t3
    unsigned mh  = __vcmpeq4(r.th, cc4) & 0x00000101u;    // b0=ml, b1=mr
    unsigned ml01 = __byte_perm(m01, mh, 0x2104);  // (ml, m0, m1, m2)
    unsigned mr01 = __byte_perm(m01, mh, 0x5321);  // (m1, m2, m3, mr)
    d.u = (mr01 + B01) - ml01;            // per-byte u+1, in [0,2]; no borrow
    d.v = ml01 + mr01 + m01 * 2u;         // per-byte, in [0,4]; IMAD-friendly
}

__device__ __forceinline__ float unpack_b(unsigned w, unsigned sel) {
    // byte -> exact float via mantissa insertion; subtract (2^23 + bias 4)
    return __uint_as_float(__byte_perm(w, 0x4B000000u, sel)) - 8388612.0f;
}

__device__ __forceinline__ void emit_row(
    const RowD& P, const RowD& C0, const RowD& N, float& acc0, float& acc1)
{
    // packed target gradients, per-byte biased by +4, range [0,8]: carry-free
    unsigned gxt_b = C0.u * 2u + P.u + N.u;     // IMAD + IADD3
    unsigned gyt_b = (N.v + 0x04040404u) - P.v;
    #pragma unroll
    for (int i = 0; i < KX; i++) {
        float gx  = fmaf(2.f, C0.a[i], P.a[i] + N.a[i]);
        float gy  = N.s[i] - P.s[i];
        float ein = fabsf(gx) + fabsf(gy);
        unsigned sel = 0x7440u + (unsigned)i;
        float etg = fabsf(unpack_b(gxt_b, sel)) + fabsf(unpack_b(gyt_b, sel));
        float d = ein - etg;
        if (i & 1) acc1 = fmaf(d, d, acc1);
        else       acc0 = fmaf(d, d, acc0);
    }
}

__global__ __launch_bounds__(WPB * 32, 7)
void edge_kernel(const float* __restrict__ inp, float* __restrict__ out)
{
    const int warp = blockIdx.x * WPB + (threadIdx.x >> 5);
    const int lane = threadIdx.x & 31;

    const int wseg = warp & (WSEG - 1);
    const int hch  = (warp >> 2) & (HCH - 1);
    const int t2   = warp >> 5;               // = b*CC + c, in [0, 304)
    const unsigned c = (unsigned)(t2 % CC);
    const int b    = t2 / CC;
    const unsigned cc4 = c * 0x01010101u;

    const int wstart = wseg * (32 * KX);
    const int w0 = wstart + lane * KX;
    const bool lok = (w0 > 0);
    const bool rok = (w0 + KX < WW);
    const int offL = lok ? (w0 - 1)  : w0;    // clamped in-bounds
    const int offR = rok ? (w0 + KX) : w0;
    const int h0 = hch * HROWS;
    const float* plane = inp + ((size_t)t2) * HH * WW;
    const unsigned char* tplane = g_tgt8 + (size_t)b * HH * WW;

    float acc0 = 0.f, acc1 = 0.f;
    RowD rA, rB, rC;
    Raw q0, q1;

    // Prologue: invariant at loop top — q0 holds row y+1, q1 holds row y+2.
    load_row(q0, plane, tplane, h0 - 1, w0, offL, offR, lok, rok);
    load_row(q1, plane, tplane, h0,     w0, offL, offR, lok, rok);
    derive(rA, q0, cc4);
    load_row(q0, plane, tplane, h0 + 1, w0, offL, offR, lok, rok);
    derive(rB, q1, cc4);
    load_row(q1, plane, tplane, h0 + 2, w0, offL, offR, lok, rok);

    int y = h0;
    // 6-phase body (LCM of 2 raw slots x 3 row regs), 10 iters = 60 rows
    #pragma unroll 1
    for (int it = 0; it < 10; ++it) {
        derive(rC, q0, cc4);
        load_row(q0, plane, tplane, y + 3, w0, offL, offR, lok, rok);
        emit_row(rA, rB, rC, acc0, acc1); ++y;
        derive(rA, q1, cc4);
        load_row(q1, plane, tplane, y + 3, w0, offL, offR, lok, rok);
        emit_row(rB, rC, rA, acc0, acc1); ++y;
        derive(rB, q0, cc4);
        load_row(q0, plane, tplane, y + 3, w0, offL, offR, lok, rok);
        emit_row(rC, rA, rB, acc0, acc1); ++y;
        derive(rC, q1, cc4);
        load_row(q1, plane, tplane, y + 3, w0, offL, offR, lok, rok);
        emit_row(rA, rB, rC, acc0, acc1); ++y;
        derive(rA, q0, cc4);
        load_row(q0, plane, tplane, y + 3, w0, offL, offR, lok, rok);
        emit_row(rB, rC, rA, acc0, acc1); ++y;
        derive(rB, q1, cc4);
        load_row(q1, plane, tplane, y + 3, w0, offL, offR, lok, rok);
        emit_row(rC, rA, rB, acc0, acc1); ++y;
    }
    // Epilogue: rows h0+60..63; loads reach exactly row h0+64 (bottom halo)
    derive(rC, q0, cc4);
    load_row(q0, plane, tplane, y + 3, w0, offL, offR, lok, rok);
    emit_row(rA, rB, rC, acc0, acc1); ++y;
    derive(rA, q1, cc4);
    load_row(q1, plane, tplane, y + 3, w0, offL, offR, lok, rok);
    emit_row(rB, rC, rA, acc0, acc1); ++y;
    derive(rB, q0, cc4); emit_row(rC, rA, rB, acc0, acc1); ++y;
    derive(rC, q1, cc4); emit_row(rA, rB, rC, acc0, acc1);

    // reduce: warp -> block -> global double; last block finalizes + resets.
    float acc = acc0 + acc1;
    #pragma unroll
    for (int o = 16; o; o >>= 1) acc += __shfl_xor_sync(0xffffffffu, acc, o);
    __shared__ float ws[WPB];
    if (lane == 0) ws[threadIdx.x >> 5] = acc;
    __syncthreads();
    if (threadIdx.x == 0) {
        double s = 0.0;
        #pragma unroll
        for (int i = 0; i < WPB; i++) s += (double)ws[i];
        atomicAdd(&g_acc, s);
        __threadfence();
        unsigned t = atomicAdd(&g_ticket, 1u);
        if (t == (unsigned)(NBLOCKS - 1)) {
            double v = atomicAdd(&g_acc, 0.0);   // ordered read
            out[0] = (float)(v * (1.0 / ((double)BB * HH * WW)));
            g_acc = 0.0;                          // reset for next replay
            g_ticket = 0u;
        }
    }
}

// ---------------------------------------------------------------------------
extern "C" void kernel_launch(void* const* d_in, const int* in_sizes, int n_in,
                              void* d_out, int out_size)
{
    const float* inp;
    const unsigned int* tgt;
    if (in_sizes[0] == BB * CC * HH * WW) {
        inp = (const float*)d_in[0];
        tgt = (const unsigned int*)d_in[1];
    } else {
        inp = (const float*)d_in[1];
        tgt = (const unsigned int*)d_in[0];
    }
    float* out = (float*)d_out;

    prep_kernel<<<1184, 256>>>(tgt);
    edge_kernel<<<NBLOCKS, WPB * 32>>>(inp, out);
}

// round 16
// speedup vs baseline: 1.2884x; 1.0034x over previous
#include <cuda_runtime.h>
#include <stdint.h>

#define BB 16
#define CC 19
#define HH 512
#define WW 512
#define HCH 8
#define HROWS (HH/HCH)    // 64
#define NBLOCKS (BB*CC*HCH)   // 2432 blocks; block = (b*CC+c, hch) strip
#define THREADS 128       // 4 warps = 4 w-segments of one 512-wide strip

#define DSTG 6            // smem ring stages
#define PD   4            // prefetch distance (rows) ~ 840 cyc > 577 DRAM
#define B01  0x01010101u

__device__ unsigned char g_tgt8[BB*HH*WW];  // 4 MB scratch (static, allowed)
__device__ double g_acc;                     // zero-init; edge's last block resets
__device__ unsigned g_ticket;

// ---------------------------------------------------------------------------
// prep: detect int64-vs-int32 targets and convert to uint8 (L2-resident for
// the 19x channel reuse). Sampling safe for the SMALLEST possible buffer.
// ---------------------------------------------------------------------------
__global__ void prep_kernel(const unsigned int* __restrict__ t) {
    bool is32 = false;
    #pragma unroll
    for (unsigned k = 0; k < 16; k++) {
        unsigned idx = k * 262139u + 1u;       // max 3,932,086 < 4,194,304
        is32 |= (__ldg(&t[idx | 1u]) != 0u);   // force odd
    }

    const int n4 = BB * HH * WW / 4;
    const uint4* tv = reinterpret_cast<const uint4*>(t);
    for (int i = blockIdx.x * blockDim.x + threadIdx.x; i < n4;
         i += gridDim.x * blockDim.x) {
        uchar4 o;
        if (is32) {
            uint4 v = tv[i];
            o.x = (unsigned char)v.x; o.y = (unsigned char)v.y;
            o.z = (unsigned char)v.z; o.w = (unsigned char)v.w;
        } else {
            uint4 v0 = tv[2 * i];
            uint4 v1 = tv[2 * i + 1];
            o.x = (unsigned char)v0.x; o.y = (unsigned char)v0.z;
            o.z = (unsigned char)v1.x; o.w = (unsigned char)v1.z;
        }
        reinterpret_cast<uchar4*>(g_tgt8)[i] = o;
    }
}

// ---------------------------------------------------------------------------
struct RowD { float a[4], s[4]; unsigned u, v; };

__device__ __forceinline__ float unpack_b(unsigned w, unsigned sel) {
    return __uint_as_float(__byte_perm(w, 0x4B000000u, sel)) - 8388612.0f;
}

__device__ __forceinline__ void emit_row(
    const RowD& P, const RowD& C0, const RowD& N, float& acc0, float& acc1)
{
    unsigned gxt_b = C0.u * 2u + P.u + N.u;
    unsigned gyt_b = (N.v + 0x04040404u) - P.v;
    #pragma unroll
    for (int i = 0; i < 4; i++) {
        float gx  = fmaf(2.f, C0.a[i], P.a[i] + N.a[i]);
        float gy  = N.s[i] - P.s[i];
        float ein = fabsf(gx) + fabsf(gy);
        unsigned sel = 0x7440u + (unsigned)i;
        float etg = fabsf(unpack_b(gxt_b, sel)) + fabsf(unpack_b(gyt_b, sel));
        float d = ein - etg;
        if (i & 1) acc1 = fmaf(d, d, acc1);
        else       acc0 = fmaf(d, d, acc0);
    }
}

#define WAIT_SYNC() do { \
    asm volatile("cp.async.wait_group 4;\n" ::: "memory"); \
    __syncthreads(); \
} while (0)

__global__ __launch_bounds__(THREADS, 7)
void edge_kernel(const float* __restrict__ inp, float* __restrict__ out)
{
    __shared__ __align__(16) float sm_f[DSTG * WW];
    __shared__ __align__(4)  unsigned char sm_t[DSTG * WW];

    const int tid = threadIdx.x;
    const int hch = blockIdx.x & (HCH - 1);
    const int t2  = blockIdx.x >> 3;          // b*CC + c, in [0, 304)
    const unsigned c = (unsigned)(t2 % CC);
    const int b = t2 / CC;
    const unsigned cc4 = c * B01;

    const int cidx = tid * 4;                  // 0..508 (block covers full 512)
    const bool lok = (cidx > 0);
    const bool rok = (cidx + 4 < WW);
    const int oL = lok ? cidx - 1 : 0;         // clamped smem column offsets
    const int oR = rok ? cidx + 4 : WW - 1;
    const int h0 = hch * HROWS;

    const float* plane = inp + (size_t)t2 * (HH * WW);
    const unsigned char* tplane = g_tgt8 + (size_t)b * (HH * WW);

    const uint32_t sf  = (uint32_t)__cvta_generic_to_shared(sm_f);
    const uint32_t stt = (uint32_t)__cvta_generic_to_shared(sm_t);

    // Issue row j (local index; global row = h0-1+j) into ring stage stg.
    // Exactly one commit per call keeps wait_group(4) accounting exact.
    auto issue = [&](int j, int stg) {
        if (j <= HROWS + 1) {                  // 66 real rows: j in [0,65]
            int row = h0 - 1 + j;
            if ((unsigned)row < (unsigned)HH) {
                const float* gs = plane + (size_t)row * WW + cidx;
                const unsigned char* gt = tplane + (size_t)row * WW + cidx;
                uint32_t df = sf  + (uint32_t)(stg * (WW * 4) + cidx * 4);
                uint32_t dt = stt + (uint32_t)(stg * WW + cidx);
                asm volatile("cp.async.cg.shared.global [%0], [%1], 16;\n"
                             :: "r"(df), "l"(gs) : "memory");
                asm volatile("cp.async.ca.shared.global [%0], [%1], 4;\n"
                             :: "r"(dt), "l"(gt) : "memory");
            } else {                           // block-uniform OOB: zero-fill
                float4 z = make_float4(0.f, 0.f, 0.f, 0.f);
                *reinterpret_cast<float4*>(sm_f + stg * WW + cidx) = z;
                *reinterpret_cast<unsigned*>(sm_t + stg * WW + cidx) = 0xFFFFFFFFu;
            }
        }
        asm volatile("cp.async.commit_group;\n" ::: "memory");
    };

    // Consume ring stage stg -> derived row terms (champion derive).
    auto consume = [&](RowD& d, int stg) {
        const float* srow = sm_f + stg * WW;
        const unsigned char* trow = sm_t + stg * WW;
        float4 xv = *reinterpret_cast<const float4*>(srow + cidx);
        float xl = lok ? srow[oL] : 0.f;       // halos: plain smem reads
        float xr = rok ? srow[oR] : 0.f;
        d.a[0] = xv.y - xl;   d.a[1] = xv.z - xv.x;
        d.a[2] = xv.w - xv.y; d.a[3] = xr - xv.z;
        d.s[0] = fmaf(2.f, xv.x, xl   + xv.y);
        d.s[1] = fmaf(2.f, xv.y, xv.x + xv.z);
        d.s[2] = fmaf(2.f, xv.z, xv.y + xv.w);
        d.s[3] = fmaf(2.f, xv.w, xv.z + xr);

        unsigned t4 = *reinterpret_cast<const unsigned*>(trow + cidx);
        unsigned tl = (unsigned)trow[oL];
        unsigned tr = (unsigned)trow[oR];
        unsigned th = (lok ? tl : 0xFFu) | ((rok ? tr : 0xFFu) << 8);
        unsigned m01 = __vcmpeq4(t4, cc4) & B01;
        unsigned mh  = __vcmpeq4(th, cc4) & 0x00000101u;
        unsigned ml01 = __byte_perm(m01, mh, 0x2104);
        unsigned mr01 = __byte_perm(m01, mh, 0x5321);
        d.u = (mr01 + B01) - ml01;
        d.v = ml01 + mr01 + m01 * 2u;
    };

    float acc0 = 0.f, acc1 = 0.f;
    RowD rA, rB, rC;

    // Prologue: fill PD groups (rows j=0..3 -> stages 0..3).
    issue(0, 0); issue(1, 1); issue(2, 2); issue(3, 3);
    // j=0,1: derive first two rows.
    issue(4, 4); WAIT_SYNC(); consume(rA, 0);
    issue(5, 5); WAIT_SYNC(); consume(rB, 1);

    // 6-phase body: j = 2+6*it+k; issue stage k, consume stage (2+k)%6.
    int ji = 6;
    #pragma unroll 1
    for (int it = 0; it < 10; ++it) {
        issue(ji++, 0); WAIT_SYNC(); consume(rC, 2); emit_row(rA, rB, rC, acc0, acc1);
        issue(ji++, 1); WAIT_SYNC(); consume(rA, 3); emit_row(rB, rC, rA, acc0, acc1);
        issue(ji++, 2); WAIT_SYNC(); consume(rB, 4); emit_row(rC, rA, rB, acc0, acc1);
        issue(ji++, 3); WAIT_SYNC(); consume(rC, 5); emit_row(rA, rB, rC, acc0, acc1);
        issue(ji++, 4); WAIT_SYNC(); consume(rA, 0); emit_row(rB, rC, rA, acc0, acc1);
        issue(ji++, 5); WAIT_SYNC(); consume(rB, 1); emit_row(rC, rA, rB, acc0, acc1);
    }
    // Epilogue: j=62..65 (issues 66..69 are empty commits, keep accounting).
    issue(ji++, 0); WAIT_SYNC(); consume(rC, 2); emit_row(rA, rB, rC, acc0, acc1);
    issue(ji++, 1); WAIT_SYNC(); consume(rA, 3); emit_row(rB, rC, rA, acc0, acc1);
    issue(ji++, 2); WAIT_SYNC(); consume(rB, 4); emit_row(rC, rA, rB, acc0, acc1);
    issue(ji++, 3); WAIT_SYNC(); consume(rC, 5); emit_row(rA, rB, rC, acc0, acc1);

    asm volatile("cp.async.wait_group 0;\n" ::: "memory");  // drain before exit

    // reduce: warp -> block -> global double; last block finalizes + resets.
    float acc = acc0 + acc1;
    #pragma unroll
    for (int o = 16; o; o >>= 1) acc += __shfl_xor_sync(0xffffffffu, acc, o);
    __shared__ float ws[4];
    if ((tid & 31) == 0) ws[tid >> 5] = acc;
    __syncthreads();
    if (tid == 0) {
        double s = 0.0;
        #pragma unroll
        for (int i = 0; i < 4; i++) s += (double)ws[i];
        atomicAdd(&g_acc, s);
        __threadfence();
        unsigned t = atomicAdd(&g_ticket, 1u);
        if (t == (unsigned)(NBLOCKS - 1)) {
            double v = atomicAdd(&g_acc, 0.0);   // ordered read
            out[0] = (float)(v * (1.0 / ((double)BB * HH * WW)));
            g_acc = 0.0;                          // reset for next replay
            g_ticket = 0u;
        }
    }
}

// ---------------------------------------------------------------------------
extern "C" void kernel_launch(void* const* d_in, const int* in_sizes, int n_in,
                              void* d_out, int out_size)
{
    const float* inp;
    const unsigned int* tgt;
    if (in_sizes[0] == BB * CC * HH * WW) {
        inp = (const float*)d_in[0];
        tgt = (const unsigned int*)d_in[1];
    } else {
        inp = (const float*)d_in[1];
        tgt = (const unsigned int*)d_in[0];
    }
    float* out = (float*)d_out;

    prep_kernel<<<1184, 256>>>(tgt);
    edge_kernel<<<NBLOCKS, THREADS>>>(inp, out);
}